// round 15
// baseline (speedup 1.0000x reference)
#include <cuda_runtime.h>
#include <cuda_fp16.h>
#include <cstdint>

// ---------------------------------------------------------------------------
// QuantumAttention: B=4, S=1024, E=1024, H=16, HD=64
// out  = [B,S,E]           -> d_out[0 .. 4194304)
// probs= [B,H,S,S] (mixed) -> d_out[4194304 .. 71303168)
// Round 14: R12 structure (best: 675.7us) + streaming cache hints (.cs) on
// the write-once/read-once streams (E, probs, ctx, out) to stop L2 thrash.
// ---------------------------------------------------------------------------

#define Bc 4
#define Sc 1024
#define Ec 1024
#define Hc 16
#define HDc 64
#define Mc (Bc * Sc)           // 4096
#define OUT_OFF (Bc * Sc * Ec) // 4194304

__device__ float g_Wq_eff[Ec * Ec];
__device__ float g_Wk_eff[Ec * Ec];
__device__ float g_bq_eff[Ec];
__device__ float g_bk_eff[Ec];
__device__ float g_Q[Bc * Hc * Sc * HDc];
__device__ float g_K[Bc * Hc * Sc * HDc];
__device__ float g_V[Bc * Hc * Sc * HDc];
__device__ float g_ctx[Bc * Hc * Sc * HDc];
__device__ float g_rowsum[Bc * Hc * Sc];
__device__ __half g_Eh[(size_t)Bc * Hc * Sc * Sc];   // 128 MB scratch (fp16)
__device__ int   g_partner[Hc];
__device__ float g_pw[Hc];
__device__ int   g_pairA[Hc / 2];
__device__ int   g_pairB[Hc / 2];

// ---------------------------------------------------------------------------
__device__ __forceinline__ uint32_t f2tf32(float x) {
    uint32_t r;
    asm("cvt.rna.tf32.f32 %0, %1;" : "=r"(r) : "f"(x));
    return r;
}

__device__ __forceinline__ void mma_tf32(float* c, const uint32_t* a,
                                         uint32_t b0, uint32_t b1) {
    asm volatile(
        "mma.sync.aligned.m16n8k8.row.col.f32.tf32.tf32.f32 "
        "{%0,%1,%2,%3}, {%4,%5,%6,%7}, {%8,%9}, {%0,%1,%2,%3};\n"
        : "+f"(c[0]), "+f"(c[1]), "+f"(c[2]), "+f"(c[3])
        : "r"(a[0]), "r"(a[1]), "r"(a[2]), "r"(a[3]), "r"(b0), "r"(b1));
}

// ---------------------------------------------------------------------------
__global__ void init_misc_kernel(const float* __restrict__ ent,
                                 const float* __restrict__ had,
                                 const float* __restrict__ phase,
                                 const float* __restrict__ bq,
                                 const float* __restrict__ bk) {
    int t = threadIdx.x;
    if (t < Hc) {
        int p = t; float w = 0.f;
        for (int h = 0; h < Hc; h++) {
            if (h != t && ent[h * Hc + t] != 0.f) { p = h; w = ent[h * Hc + t]; }
        }
        g_partner[t] = p;
        g_pw[t] = w;
    }
    __syncthreads();
    if (t == 0) {
        int c = 0;
        for (int g = 0; g < Hc; g++) {
            int p = g_partner[g];
            if (p >= g) { g_pairA[c] = g; g_pairB[c] = p; c++; }
        }
    }
    for (int j = t; j < Ec; j += blockDim.x) {
        int h = j >> 6, e = j & 63;
        float aq = 0.f, ak = 0.f;
        for (int d = 0; d < HDc; d++) {
            float hv = had[d * HDc + e];
            aq += hv * bq[h * HDc + d];
            ak += hv * bk[h * HDc + d];
        }
        float c = cosf(phase[j]);
        g_bq_eff[j] = c * aq;
        g_bk_eff[j] = c * ak;
    }
}

__global__ void zero_rowsum_kernel() {
    int i = blockIdx.x * blockDim.x + threadIdx.x;
    if (i < Bc * Hc * Sc) g_rowsum[i] = 0.f;
}

// ---------------------------------------------------------------------------
// Merged weight transform (z = 0: Wq, z = 1: Wk). grid: (16, 16, 2)
// ---------------------------------------------------------------------------
__global__ __launch_bounds__(256) void wtrans_kernel(const float* __restrict__ Wq,
                                                     const float* __restrict__ Wk,
                                                     const float* __restrict__ had,
                                                     const float* __restrict__ phase) {
    const int which = blockIdx.z;
    const float* W = which ? Wk : Wq;
    float* Weff = which ? g_Wk_eff : g_Wq_eff;
    __shared__ float sH[HDc * 65];
    __shared__ float sW[HDc][68];
    __shared__ float sc[HDc];
    const int h = blockIdx.x;
    const int i0 = blockIdx.y * 64;
    const int t = threadIdx.x;
    for (int j = t; j < HDc * HDc; j += 256) {
        int d = j >> 6, e = j & 63;
        sH[d * 65 + e] = had[j];
    }
    if (t < HDc) sc[t] = cosf(phase[h * HDc + t]);
#pragma unroll
    for (int i = 0; i < 4; i++) {
        int idx = i * 256 + t;
        int d = idx >> 4, q = (idx & 15) * 4;
        *(float4*)&sW[d][q] = *(const float4*)&W[(h * HDc + d) * Ec + i0 + q];
    }
    __syncthreads();

    const int tx = t & 15;
    const int ty = t >> 4;
    float acc[4][4];
#pragma unroll
    for (int a = 0; a < 4; a++)
#pragma unroll
        for (int b = 0; b < 4; b++) acc[a][b] = 0.f;

#pragma unroll 8
    for (int d = 0; d < HDc; d++) {
        float4 w = *(const float4*)&sW[d][tx * 4];
#pragma unroll
        for (int ee = 0; ee < 4; ee++) {
            float hv = sH[d * 65 + ty * 4 + ee];
            acc[ee][0] += hv * w.x;
            acc[ee][1] += hv * w.y;
            acc[ee][2] += hv * w.z;
            acc[ee][3] += hv * w.w;
        }
    }
#pragma unroll
    for (int ee = 0; ee < 4; ee++) {
        int e = ty * 4 + ee;
        float s = sc[e];
        float4 o = make_float4(s * acc[ee][0], s * acc[ee][1],
                               s * acc[ee][2], s * acc[ee][3]);
        *(float4*)&Weff[(h * HDc + e) * Ec + i0 + tx * 4] = o;
    }
}

// ---------------------------------------------------------------------------
// GEMM inner tile: [row][k] layout, stride 68 words (R9, proven).
// ---------------------------------------------------------------------------
#define GEMM_MMA_TILE(As, Bs, acc, wm, wn, gid, tig, NKS)                     \
    _Pragma("unroll")                                                         \
    for (int ks = 0; ks < NKS; ks++) {                                        \
        int kb = ks * 8;                                                      \
        uint32_t a[2][4];                                                     \
        _Pragma("unroll")                                                     \
        for (int mi = 0; mi < 2; mi++) {                                      \
            int r = (wm) + mi * 16 + (gid);                                   \
            a[mi][0] = (As)[r][kb + (tig)];                                   \
            a[mi][1] = (As)[r + 8][kb + (tig)];                               \
            a[mi][2] = (As)[r][kb + (tig) + 4];                               \
            a[mi][3] = (As)[r + 8][kb + (tig) + 4];                           \
        }                                                                     \
        _Pragma("unroll")                                                     \
        for (int ni = 0; ni < 8; ni++) {                                      \
            int c = (wn) + ni * 8 + (gid);                                    \
            uint32_t b0 = (Bs)[c][kb + (tig)];                                \
            uint32_t b1 = (Bs)[c][kb + (tig) + 4];                            \
            mma_tf32(acc[0][ni], a[0], b0, b1);                               \
            mma_tf32(acc[1][ni], a[1], b0, b1);                               \
        }                                                                     \
    }

#define GEMM_FILL4(Sm, row, kq, v)                                            \
    do {                                                                      \
        uint4 _u = make_uint4(f2tf32((v).x), f2tf32((v).y),                   \
                              f2tf32((v).z), f2tf32((v).w));                  \
        *(uint4*)&(Sm)[row][kq] = _u;                                         \
    } while (0)

// ---------------------------------------------------------------------------
// Merged TF32 projection GEMM (z selects q/k/v). grid: (8, 32, 3)
// ---------------------------------------------------------------------------
__global__ __launch_bounds__(256) void gemm_tf32_proj(
    const float* __restrict__ Aq, const float* __restrict__ Ak,
    const float* __restrict__ Av, const float* __restrict__ Wv,
    const float* __restrict__ bv) {
    const int which = blockIdx.z;
    const float* A    = (which == 0) ? Aq : (which == 1) ? Ak : Av;
    const float* W    = (which == 0) ? g_Wq_eff : (which == 1) ? g_Wk_eff : Wv;
    const float* bias = (which == 0) ? g_bq_eff : (which == 1) ? g_bk_eff : bv;
    float* Out        = (which == 0) ? g_Q : (which == 1) ? g_K : g_V;

    __shared__ uint32_t As[128][68];
    __shared__ uint32_t Bs[128][68];
    const int t = threadIdx.x;
    const int lane = t & 31, warp = t >> 5;
    const int gid = lane >> 2, tig = lane & 3;
    const int wm = (warp & 3) * 32, wn = (warp >> 2) * 64;
    const int m0 = blockIdx.y * 128, n0 = blockIdx.x * 128;

    float acc[2][8][4];
#pragma unroll
    for (int mi = 0; mi < 2; mi++)
#pragma unroll
        for (int ni = 0; ni < 8; ni++)
#pragma unroll
            for (int j = 0; j < 4; j++) acc[mi][ni][j] = 0.f;

    for (int k0 = 0; k0 < Ec; k0 += 64) {
#pragma unroll
        for (int i = 0; i < 8; i++) {
            int idx = i * 256 + t;
            int row = idx >> 4, kq = (idx & 15) * 4;
            float4 va = *(const float4*)&A[(m0 + row) * Ec + k0 + kq];
            GEMM_FILL4(As, row, kq, va);
            float4 vb = *(const float4*)&W[(n0 + row) * Ec + k0 + kq];
            GEMM_FILL4(Bs, row, kq, vb);
        }
        __syncthreads();
        GEMM_MMA_TILE(As, Bs, acc, wm, wn, gid, tig, 8)
        __syncthreads();
    }

#pragma unroll
    for (int mi = 0; mi < 2; mi++) {
        int r0 = m0 + wm + mi * 16 + gid;
#pragma unroll
        for (int ni = 0; ni < 8; ni++) {
            int col = n0 + wn + ni * 8 + tig * 2;
            float bb0 = bias[col], bb1 = bias[col + 1];
            int h = col >> 6, d = col & 63;
            {
                int m = r0, b = m >> 10, s = m & 1023;
                *(float2*)&Out[((b * Hc + h) * Sc + s) * HDc + d] =
                    make_float2(acc[mi][ni][0] + bb0, acc[mi][ni][1] + bb1);
            }
            {
                int m = r0 + 8, b = m >> 10, s = m & 1023;
                *(float2*)&Out[((b * Hc + h) * Sc + s) * HDc + d] =
                    make_float2(acc[mi][ni][2] + bb0, acc[mi][ni][3] + bb1);
            }
        }
    }
}

// ---------------------------------------------------------------------------
// TF32 scores: E(fp16, .cs) = exp(Q K^T / 8) + fp32 row sums. grid: (8, 8, 64)
// ---------------------------------------------------------------------------
__global__ __launch_bounds__(256) void scores_kernel() {
    __shared__ uint32_t As[128][68];
    __shared__ uint32_t Bs[128][68];
    __shared__ float rs[128];
    const int t = threadIdx.x;
    const int lane = t & 31, warp = t >> 5;
    const int gid = lane >> 2, tig = lane & 3;
    const int wm = (warp & 3) * 32, wn = (warp >> 2) * 64;
    const int bh = blockIdx.z;
    const int m0 = blockIdx.y * 128, n0 = blockIdx.x * 128;
    const float* Qb = g_Q + (size_t)bh * Sc * HDc;
    const float* Kb = g_K + (size_t)bh * Sc * HDc;

    float acc[2][8][4];
#pragma unroll
    for (int mi = 0; mi < 2; mi++)
#pragma unroll
        for (int ni = 0; ni < 8; ni++)
#pragma unroll
            for (int j = 0; j < 4; j++) acc[mi][ni][j] = 0.f;

#pragma unroll
    for (int i = 0; i < 8; i++) {
        int idx = i * 256 + t;
        int row = idx >> 4, kq = (idx & 15) * 4;
        float4 va = *(const float4*)&Qb[(m0 + row) * HDc + kq];
        GEMM_FILL4(As, row, kq, va);
        float4 vb = *(const float4*)&Kb[(n0 + row) * HDc + kq];
        GEMM_FILL4(Bs, row, kq, vb);
    }
    __syncthreads();
    GEMM_MMA_TILE(As, Bs, acc, wm, wn, gid, tig, 8)

    if (t < 128) rs[t] = 0.f;
    __syncthreads();

    __half* Eb = g_Eh + (size_t)bh * Sc * Sc;
#pragma unroll
    for (int mi = 0; mi < 2; mi++) {
        int r0 = wm + mi * 16 + gid;
        float rsum0 = 0.f, rsum1 = 0.f;
#pragma unroll
        for (int ni = 0; ni < 8; ni++) {
            int col = n0 + wn + ni * 8 + tig * 2;
            float e0 = __expf(acc[mi][ni][0] * 0.125f);
            float e1 = __expf(acc[mi][ni][1] * 0.125f);
            float e2 = __expf(acc[mi][ni][2] * 0.125f);
            float e3 = __expf(acc[mi][ni][3] * 0.125f);
            __half2 h01 = __floats2half2_rn(e0, e1);
            __half2 h23 = __floats2half2_rn(e2, e3);
            __stcs((unsigned int*)&Eb[(size_t)(m0 + r0) * Sc + col],
                   *(unsigned int*)&h01);
            __stcs((unsigned int*)&Eb[(size_t)(m0 + r0 + 8) * Sc + col],
                   *(unsigned int*)&h23);
            rsum0 += e0 + e1;
            rsum1 += e2 + e3;
        }
        atomicAdd(&rs[r0], rsum0);
        atomicAdd(&rs[r0 + 8], rsum1);
    }
    __syncthreads();
    if (t < 128) atomicAdd(&g_rowsum[bh * Sc + m0 + t], rs[t]);
}

// ---------------------------------------------------------------------------
// Pair-symmetric mix + probs + ctx (TF32 mma). CTA = (b, pair, 64 q rows),
// 32-key chunks. E read .cs (fp16), probs written .cs, ctx written .cs.
// grid: (16, 32), 256 threads
// ---------------------------------------------------------------------------
__global__ __launch_bounds__(256) void mixctx_pair_kernel(float* __restrict__ Pout) {
    __shared__ uint32_t Ag[32][68];
    __shared__ uint32_t Ap[32][68];
    __shared__ uint32_t Vg[32][68];
    __shared__ uint32_t Vp[32][68];
    __shared__ float ivg[64], ivp[64], ivgw[64], ivpw[64];

    const int t = threadIdx.x;
    const int lane = t & 31, warp = t >> 5;
    const int gid = lane >> 2, tig = lane & 3;
    const int bp = blockIdx.y;
    const int b = bp >> 3, pr = bp & 7;
    const int g = g_pairA[pr], p = g_pairB[pr];
    const int q0 = blockIdx.x * 64;

    if (t < 64) {
        float rg = g_rowsum[(b * Hc + g) * Sc + q0 + t];
        float rp = g_rowsum[(b * Hc + p) * Sc + q0 + t];
        float w = g_pw[g];
        ivg[t] = 1.f / rg;
        ivp[t] = 1.f / rp;
        ivpw[t] = w / rp;
        ivgw[t] = w / rg;
    }
    __syncthreads();

    const __half* Eg = g_Eh + (size_t)(b * Hc + g) * Sc * Sc;
    const __half* Ep = g_Eh + (size_t)(b * Hc + p) * Sc * Sc;
    const float* VgB = g_V + (size_t)(b * Hc + g) * Sc * HDc;
    const float* VpB = g_V + (size_t)(b * Hc + p) * Sc * HDc;
    float* Pg = Pout + (size_t)(b * Hc + g) * Sc * Sc;
    float* Pp = Pout + (size_t)(b * Hc + p) * Sc * Sc;

    float acc[8][4];
#pragma unroll
    for (int ni = 0; ni < 8; ni++)
#pragma unroll
        for (int j = 0; j < 4; j++) acc[ni][j] = 0.f;

    const int row = t >> 2;                 // 0..63
    const int kbase = (t & 3) * 8;          // 0,8,16,24
    const float vg1 = ivg[row], vpw = ivpw[row];
    const float vp1 = ivp[row], vgw = ivgw[row];
    const int vr = t >> 3, vc0 = (t & 7) * 8;

    for (int kt = 0; kt < Sc; kt += 32) {
        // E chunk (8 halves per head per thread), mix, write probs, stage tf32
        {
            uint4 ug = __ldcs((const uint4*)(Eg + (size_t)(q0 + row) * Sc + kt + kbase));
            uint4 up = __ldcs((const uint4*)(Ep + (size_t)(q0 + row) * Sc + kt + kbase));
            float2 eg0 = __half22float2(*(__half2*)&ug.x);
            float2 eg1 = __half22float2(*(__half2*)&ug.y);
            float2 eg2 = __half22float2(*(__half2*)&ug.z);
            float2 eg3 = __half22float2(*(__half2*)&ug.w);
            float2 ep0 = __half22float2(*(__half2*)&up.x);
            float2 ep1 = __half22float2(*(__half2*)&up.y);
            float2 ep2 = __half22float2(*(__half2*)&up.z);
            float2 ep3 = __half22float2(*(__half2*)&up.w);
            float egv[8] = {eg0.x, eg0.y, eg1.x, eg1.y, eg2.x, eg2.y, eg3.x, eg3.y};
            float epv[8] = {ep0.x, ep0.y, ep1.x, ep1.y, ep2.x, ep2.y, ep3.x, ep3.y};
            float pgv[8], ppv[8];
#pragma unroll
            for (int i = 0; i < 8; i++) {
                pgv[i] = egv[i] * vg1 + epv[i] * vpw;
                ppv[i] = epv[i] * vp1 + egv[i] * vgw;
            }
            float* PgR = Pg + (size_t)(q0 + row) * Sc + kt + kbase;
            float* PpR = Pp + (size_t)(q0 + row) * Sc + kt + kbase;
            __stcs((float4*)(PgR),     make_float4(pgv[0], pgv[1], pgv[2], pgv[3]));
            __stcs((float4*)(PgR + 4), make_float4(pgv[4], pgv[5], pgv[6], pgv[7]));
            __stcs((float4*)(PpR),     make_float4(ppv[0], ppv[1], ppv[2], ppv[3]));
            __stcs((float4*)(PpR + 4), make_float4(ppv[4], ppv[5], ppv[6], ppv[7]));
#pragma unroll
            for (int i = 0; i < 8; i++) {
                Ag[kbase + i][row] = f2tf32(pgv[i]);
                Ap[kbase + i][row] = f2tf32(ppv[i]);
            }
        }
        // V chunks [32 k x 64 d] for both heads (keep cached: reused by CTAs)
#pragma unroll
        for (int i = 0; i < 2; i++) {
            float4 v0 = *(const float4*)&VgB[(size_t)(kt + vr) * HDc + vc0 + 4 * i];
            Vg[vr][vc0 + 4 * i + 0] = f2tf32(v0.x); Vg[vr][vc0 + 4 * i + 1] = f2tf32(v0.y);
            Vg[vr][vc0 + 4 * i + 2] = f2tf32(v0.z); Vg[vr][vc0 + 4 * i + 3] = f2tf32(v0.w);
            float4 v1 = *(const float4*)&VpB[(size_t)(kt + vr) * HDc + vc0 + 4 * i];
            Vp[vr][vc0 + 4 * i + 0] = f2tf32(v1.x); Vp[vr][vc0 + 4 * i + 1] = f2tf32(v1.y);
            Vp[vr][vc0 + 4 * i + 2] = f2tf32(v1.z); Vp[vr][vc0 + 4 * i + 3] = f2tf32(v1.w);
        }
        __syncthreads();

        uint32_t (*Asl)[68] = (warp < 4) ? Ag : Ap;
        uint32_t (*Vsl)[68] = (warp < 4) ? Vg : Vp;
        const int wm = (warp & 3) * 16;
#pragma unroll
        for (int ks = 0; ks < 4; ks++) {
            int kb = ks * 8;
            uint32_t a[4];
            a[0] = Asl[kb + tig][wm + gid];
            a[1] = Asl[kb + tig][wm + gid + 8];
            a[2] = Asl[kb + tig + 4][wm + gid];
            a[3] = Asl[kb + tig + 4][wm + gid + 8];
#pragma unroll
            for (int ni = 0; ni < 8; ni++) {
                uint32_t b0 = Vsl[kb + tig][ni * 8 + gid];
                uint32_t b1 = Vsl[kb + tig + 4][ni * 8 + gid];
                mma_tf32(acc[ni], a, b0, b1);
            }
        }
        __syncthreads();
    }

    const int h = (warp < 4) ? g : p;
    const int wm = (warp & 3) * 16;
    float* Cb = g_ctx + ((size_t)(b * Hc + h) * Sc + q0) * HDc;
#pragma unroll
    for (int ni = 0; ni < 8; ni++) {
        int d = ni * 8 + tig * 2;
        __stcs((float2*)&Cb[(wm + gid) * HDc + d],
               make_float2(acc[ni][0], acc[ni][1]));
        __stcs((float2*)&Cb[(wm + gid + 8) * HDc + d],
               make_float2(acc[ni][2], acc[ni][3]));
    }
}

// ---------------------------------------------------------------------------
// TF32 output projection: out[4096,1024] = ctx_flat @ Wo^T + bo. grid: (8, 32)
// ---------------------------------------------------------------------------
__global__ __launch_bounds__(256) void gemm_tf32_out(
    const float* __restrict__ W, const float* __restrict__ bias,
    float* __restrict__ Out) {
    __shared__ uint32_t As[128][68];
    __shared__ uint32_t Bs[128][68];
    const int t = threadIdx.x;
    const int lane = t & 31, warp = t >> 5;
    const int gid = lane >> 2, tig = lane & 3;
    const int wm = (warp & 3) * 32, wn = (warp >> 2) * 64;
    const int m0 = blockIdx.y * 128, n0 = blockIdx.x * 128;

    float acc[2][8][4];
#pragma unroll
    for (int mi = 0; mi < 2; mi++)
#pragma unroll
        for (int ni = 0; ni < 8; ni++)
#pragma unroll
            for (int j = 0; j < 4; j++) acc[mi][ni][j] = 0.f;

    for (int k0 = 0; k0 < Ec; k0 += 64) {
#pragma unroll
        for (int i = 0; i < 8; i++) {
            int idx = i * 256 + t;
            int row = idx >> 4, kq = (idx & 15) * 4;
            int k = k0 + kq;
            int m = m0 + row, b = m >> 10, s = m & 1023;
            float4 va = *(const float4*)&g_ctx[((b * Hc + (k >> 6)) * Sc + s) * HDc + (k & 63)];
            GEMM_FILL4(As, row, kq, va);
            float4 vb = *(const float4*)&W[(n0 + row) * Ec + k];
            GEMM_FILL4(Bs, row, kq, vb);
        }
        __syncthreads();
        GEMM_MMA_TILE(As, Bs, acc, wm, wn, gid, tig, 8)
        __syncthreads();
    }

#pragma unroll
    for (int mi = 0; mi < 2; mi++) {
        int r0 = m0 + wm + mi * 16 + gid;
#pragma unroll
        for (int ni = 0; ni < 8; ni++) {
            int col = n0 + wn + ni * 8 + tig * 2;
            float bb0 = bias[col], bb1 = bias[col + 1];
            __stcs((float2*)&Out[r0 * Ec + col],
                   make_float2(acc[mi][ni][0] + bb0, acc[mi][ni][1] + bb1));
            __stcs((float2*)&Out[(r0 + 8) * Ec + col],
                   make_float2(acc[mi][ni][2] + bb0, acc[mi][ni][3] + bb1));
        }
    }
}

// ---------------------------------------------------------------------------
extern "C" void kernel_launch(void* const* d_in, const int* in_sizes, int n_in,
                              void* d_out, int out_size) {
    const float* query    = (const float*)d_in[0];
    const float* key      = (const float*)d_in[1];
    const float* value    = (const float*)d_in[2];
    const float* Wq       = (const float*)d_in[3];
    const float* bq       = (const float*)d_in[4];
    const float* Wk       = (const float*)d_in[5];
    const float* bk       = (const float*)d_in[6];
    const float* Wv       = (const float*)d_in[7];
    const float* bv       = (const float*)d_in[8];
    const float* Wo       = (const float*)d_in[9];
    const float* bo       = (const float*)d_in[10];
    const float* phase    = (const float*)d_in[11];
    const float* hadamard = (const float*)d_in[12];
    const float* ent      = (const float*)d_in[13];

    float* out   = (float*)d_out;
    float* probs = out + OUT_OFF;

    init_misc_kernel<<<1, 256>>>(ent, hadamard, phase, bq, bk);
    zero_rowsum_kernel<<<(Bc * Hc * Sc) / 256, 256>>>();
    wtrans_kernel<<<dim3(Hc, 16, 2), 256>>>(Wq, Wk, hadamard, phase);

    gemm_tf32_proj<<<dim3(Ec / 128, Mc / 128, 3), 256>>>(query, key, value, Wv, bv);

    scores_kernel<<<dim3(Sc / 128, Sc / 128, Bc * Hc), 256>>>();
    mixctx_pair_kernel<<<dim3(Sc / 64, Bc * 8), 256>>>(probs);
    gemm_tf32_out<<<dim3(Ec / 128, Mc / 128), 256>>>(Wo, bo, out);
}

// round 16
// speedup vs baseline: 1.5162x; 1.5162x over previous
#include <cuda_runtime.h>
#include <cuda_fp16.h>
#include <cstdint>

// ---------------------------------------------------------------------------
// QuantumAttention: B=4, S=1024, E=1024, H=16, HD=64
// out  = [B,S,E]           -> d_out[0 .. 4194304)
// probs= [B,H,S,S] (mixed) -> d_out[4194304 .. 71303168)
// Round 15: exact revert to R12 (best: 675.7us). Only delta: scores rowsum
// reduced via shfl before shared atomic (4x fewer shared atomics).
// NO cache hints anywhere (R14 showed .cs is harmful on sm_103a).
// ---------------------------------------------------------------------------

#define Bc 4
#define Sc 1024
#define Ec 1024
#define Hc 16
#define HDc 64
#define Mc (Bc * Sc)           // 4096
#define OUT_OFF (Bc * Sc * Ec) // 4194304

__device__ float g_Wq_eff[Ec * Ec];
__device__ float g_Wk_eff[Ec * Ec];
__device__ float g_bq_eff[Ec];
__device__ float g_bk_eff[Ec];
__device__ float g_Q[Bc * Hc * Sc * HDc];
__device__ float g_K[Bc * Hc * Sc * HDc];
__device__ float g_V[Bc * Hc * Sc * HDc];
__device__ float g_ctx[Bc * Hc * Sc * HDc];
__device__ float g_rowsum[Bc * Hc * Sc];
__device__ __half g_Eh[(size_t)Bc * Hc * Sc * Sc];   // 128 MB scratch (fp16)
__device__ int   g_partner[Hc];
__device__ float g_pw[Hc];
__device__ int   g_pairA[Hc / 2];
__device__ int   g_pairB[Hc / 2];

// ---------------------------------------------------------------------------
__device__ __forceinline__ uint32_t f2tf32(float x) {
    uint32_t r;
    asm("cvt.rna.tf32.f32 %0, %1;" : "=r"(r) : "f"(x));
    return r;
}

__device__ __forceinline__ void mma_tf32(float* c, const uint32_t* a,
                                         uint32_t b0, uint32_t b1) {
    asm volatile(
        "mma.sync.aligned.m16n8k8.row.col.f32.tf32.tf32.f32 "
        "{%0,%1,%2,%3}, {%4,%5,%6,%7}, {%8,%9}, {%0,%1,%2,%3};\n"
        : "+f"(c[0]), "+f"(c[1]), "+f"(c[2]), "+f"(c[3])
        : "r"(a[0]), "r"(a[1]), "r"(a[2]), "r"(a[3]), "r"(b0), "r"(b1));
}

// ---------------------------------------------------------------------------
__global__ void init_misc_kernel(const float* __restrict__ ent,
                                 const float* __restrict__ had,
                                 const float* __restrict__ phase,
                                 const float* __restrict__ bq,
                                 const float* __restrict__ bk) {
    int t = threadIdx.x;
    if (t < Hc) {
        int p = t; float w = 0.f;
        for (int h = 0; h < Hc; h++) {
            if (h != t && ent[h * Hc + t] != 0.f) { p = h; w = ent[h * Hc + t]; }
        }
        g_partner[t] = p;
        g_pw[t] = w;
    }
    __syncthreads();
    if (t == 0) {
        int c = 0;
        for (int g = 0; g < Hc; g++) {
            int p = g_partner[g];
            if (p >= g) { g_pairA[c] = g; g_pairB[c] = p; c++; }
        }
    }
    for (int j = t; j < Ec; j += blockDim.x) {
        int h = j >> 6, e = j & 63;
        float aq = 0.f, ak = 0.f;
        for (int d = 0; d < HDc; d++) {
            float hv = had[d * HDc + e];
            aq += hv * bq[h * HDc + d];
            ak += hv * bk[h * HDc + d];
        }
        float c = cosf(phase[j]);
        g_bq_eff[j] = c * aq;
        g_bk_eff[j] = c * ak;
    }
}

__global__ void zero_rowsum_kernel() {
    int i = blockIdx.x * blockDim.x + threadIdx.x;
    if (i < Bc * Hc * Sc) g_rowsum[i] = 0.f;
}

// ---------------------------------------------------------------------------
// Merged weight transform (z = 0: Wq, z = 1: Wk). grid: (16, 16, 2)
// ---------------------------------------------------------------------------
__global__ __launch_bounds__(256) void wtrans_kernel(const float* __restrict__ Wq,
                                                     const float* __restrict__ Wk,
                                                     const float* __restrict__ had,
                                                     const float* __restrict__ phase) {
    const int which = blockIdx.z;
    const float* W = which ? Wk : Wq;
    float* Weff = which ? g_Wk_eff : g_Wq_eff;
    __shared__ float sH[HDc * 65];
    __shared__ float sW[HDc][68];
    __shared__ float sc[HDc];
    const int h = blockIdx.x;
    const int i0 = blockIdx.y * 64;
    const int t = threadIdx.x;
    for (int j = t; j < HDc * HDc; j += 256) {
        int d = j >> 6, e = j & 63;
        sH[d * 65 + e] = had[j];
    }
    if (t < HDc) sc[t] = cosf(phase[h * HDc + t]);
#pragma unroll
    for (int i = 0; i < 4; i++) {
        int idx = i * 256 + t;
        int d = idx >> 4, q = (idx & 15) * 4;
        *(float4*)&sW[d][q] = *(const float4*)&W[(h * HDc + d) * Ec + i0 + q];
    }
    __syncthreads();

    const int tx = t & 15;
    const int ty = t >> 4;
    float acc[4][4];
#pragma unroll
    for (int a = 0; a < 4; a++)
#pragma unroll
        for (int b = 0; b < 4; b++) acc[a][b] = 0.f;

#pragma unroll 8
    for (int d = 0; d < HDc; d++) {
        float4 w = *(const float4*)&sW[d][tx * 4];
#pragma unroll
        for (int ee = 0; ee < 4; ee++) {
            float hv = sH[d * 65 + ty * 4 + ee];
            acc[ee][0] += hv * w.x;
            acc[ee][1] += hv * w.y;
            acc[ee][2] += hv * w.z;
            acc[ee][3] += hv * w.w;
        }
    }
#pragma unroll
    for (int ee = 0; ee < 4; ee++) {
        int e = ty * 4 + ee;
        float s = sc[e];
        float4 o = make_float4(s * acc[ee][0], s * acc[ee][1],
                               s * acc[ee][2], s * acc[ee][3]);
        *(float4*)&Weff[(h * HDc + e) * Ec + i0 + tx * 4] = o;
    }
}

// ---------------------------------------------------------------------------
// GEMM inner tile: [row][k] layout, stride 68 words (R9, proven).
// ---------------------------------------------------------------------------
#define GEMM_MMA_TILE(As, Bs, acc, wm, wn, gid, tig, NKS)                     \
    _Pragma("unroll")                                                         \
    for (int ks = 0; ks < NKS; ks++) {                                        \
        int kb = ks * 8;                                                      \
        uint32_t a[2][4];                                                     \
        _Pragma("unroll")                                                     \
        for (int mi = 0; mi < 2; mi++) {                                      \
            int r = (wm) + mi * 16 + (gid);                                   \
            a[mi][0] = (As)[r][kb + (tig)];                                   \
            a[mi][1] = (As)[r + 8][kb + (tig)];                               \
            a[mi][2] = (As)[r][kb + (tig) + 4];                               \
            a[mi][3] = (As)[r + 8][kb + (tig) + 4];                           \
        }                                                                     \
        _Pragma("unroll")                                                     \
        for (int ni = 0; ni < 8; ni++) {                                      \
            int c = (wn) + ni * 8 + (gid);                                    \
            uint32_t b0 = (Bs)[c][kb + (tig)];                                \
            uint32_t b1 = (Bs)[c][kb + (tig) + 4];                            \
            mma_tf32(acc[0][ni], a[0], b0, b1);                               \
            mma_tf32(acc[1][ni], a[1], b0, b1);                               \
        }                                                                     \
    }

#define GEMM_FILL4(Sm, row, kq, v)                                            \
    do {                                                                      \
        uint4 _u = make_uint4(f2tf32((v).x), f2tf32((v).y),                   \
                              f2tf32((v).z), f2tf32((v).w));                  \
        *(uint4*)&(Sm)[row][kq] = _u;                                         \
    } while (0)

// ---------------------------------------------------------------------------
// Merged TF32 projection GEMM (z selects q/k/v). grid: (8, 32, 3)
// ---------------------------------------------------------------------------
__global__ __launch_bounds__(256) void gemm_tf32_proj(
    const float* __restrict__ Aq, const float* __restrict__ Ak,
    const float* __restrict__ Av, const float* __restrict__ Wv,
    const float* __restrict__ bv) {
    const int which = blockIdx.z;
    const float* A    = (which == 0) ? Aq : (which == 1) ? Ak : Av;
    const float* W    = (which == 0) ? g_Wq_eff : (which == 1) ? g_Wk_eff : Wv;
    const float* bias = (which == 0) ? g_bq_eff : (which == 1) ? g_bk_eff : bv;
    float* Out        = (which == 0) ? g_Q : (which == 1) ? g_K : g_V;

    __shared__ uint32_t As[128][68];
    __shared__ uint32_t Bs[128][68];
    const int t = threadIdx.x;
    const int lane = t & 31, warp = t >> 5;
    const int gid = lane >> 2, tig = lane & 3;
    const int wm = (warp & 3) * 32, wn = (warp >> 2) * 64;
    const int m0 = blockIdx.y * 128, n0 = blockIdx.x * 128;

    float acc[2][8][4];
#pragma unroll
    for (int mi = 0; mi < 2; mi++)
#pragma unroll
        for (int ni = 0; ni < 8; ni++)
#pragma unroll
            for (int j = 0; j < 4; j++) acc[mi][ni][j] = 0.f;

    for (int k0 = 0; k0 < Ec; k0 += 64) {
#pragma unroll
        for (int i = 0; i < 8; i++) {
            int idx = i * 256 + t;
            int row = idx >> 4, kq = (idx & 15) * 4;
            float4 va = *(const float4*)&A[(m0 + row) * Ec + k0 + kq];
            GEMM_FILL4(As, row, kq, va);
            float4 vb = *(const float4*)&W[(n0 + row) * Ec + k0 + kq];
            GEMM_FILL4(Bs, row, kq, vb);
        }
        __syncthreads();
        GEMM_MMA_TILE(As, Bs, acc, wm, wn, gid, tig, 8)
        __syncthreads();
    }

#pragma unroll
    for (int mi = 0; mi < 2; mi++) {
        int r0 = m0 + wm + mi * 16 + gid;
#pragma unroll
        for (int ni = 0; ni < 8; ni++) {
            int col = n0 + wn + ni * 8 + tig * 2;
            float bb0 = bias[col], bb1 = bias[col + 1];
            int h = col >> 6, d = col & 63;
            {
                int m = r0, b = m >> 10, s = m & 1023;
                *(float2*)&Out[((b * Hc + h) * Sc + s) * HDc + d] =
                    make_float2(acc[mi][ni][0] + bb0, acc[mi][ni][1] + bb1);
            }
            {
                int m = r0 + 8, b = m >> 10, s = m & 1023;
                *(float2*)&Out[((b * Hc + h) * Sc + s) * HDc + d] =
                    make_float2(acc[mi][ni][2] + bb0, acc[mi][ni][3] + bb1);
            }
        }
    }
}

// ---------------------------------------------------------------------------
// TF32 scores: E(fp16) = exp(Q K^T / 8) + fp32 row sums. grid: (8, 8, 64)
// Rowsum partials reduced across the quad (shfl) before shared atomics.
// ---------------------------------------------------------------------------
__global__ __launch_bounds__(256) void scores_kernel() {
    __shared__ uint32_t As[128][68];
    __shared__ uint32_t Bs[128][68];
    __shared__ float rs[128];
    const int t = threadIdx.x;
    const int lane = t & 31, warp = t >> 5;
    const int gid = lane >> 2, tig = lane & 3;
    const int wm = (warp & 3) * 32, wn = (warp >> 2) * 64;
    const int bh = blockIdx.z;
    const int m0 = blockIdx.y * 128, n0 = blockIdx.x * 128;
    const float* Qb = g_Q + (size_t)bh * Sc * HDc;
    const float* Kb = g_K + (size_t)bh * Sc * HDc;

    float acc[2][8][4];
#pragma unroll
    for (int mi = 0; mi < 2; mi++)
#pragma unroll
        for (int ni = 0; ni < 8; ni++)
#pragma unroll
            for (int j = 0; j < 4; j++) acc[mi][ni][j] = 0.f;

#pragma unroll
    for (int i = 0; i < 8; i++) {
        int idx = i * 256 + t;
        int row = idx >> 4, kq = (idx & 15) * 4;
        float4 va = *(const float4*)&Qb[(m0 + row) * HDc + kq];
        GEMM_FILL4(As, row, kq, va);
        float4 vb = *(const float4*)&Kb[(n0 + row) * HDc + kq];
        GEMM_FILL4(Bs, row, kq, vb);
    }
    __syncthreads();
    GEMM_MMA_TILE(As, Bs, acc, wm, wn, gid, tig, 8)

    if (t < 128) rs[t] = 0.f;
    __syncthreads();

    __half* Eb = g_Eh + (size_t)bh * Sc * Sc;
#pragma unroll
    for (int mi = 0; mi < 2; mi++) {
        int r0 = wm + mi * 16 + gid;
        float rsum0 = 0.f, rsum1 = 0.f;
#pragma unroll
        for (int ni = 0; ni < 8; ni++) {
            int col = n0 + wn + ni * 8 + tig * 2;
            float e0 = __expf(acc[mi][ni][0] * 0.125f);
            float e1 = __expf(acc[mi][ni][1] * 0.125f);
            float e2 = __expf(acc[mi][ni][2] * 0.125f);
            float e3 = __expf(acc[mi][ni][3] * 0.125f);
            *(__half2*)&Eb[(size_t)(m0 + r0) * Sc + col]     = __floats2half2_rn(e0, e1);
            *(__half2*)&Eb[(size_t)(m0 + r0 + 8) * Sc + col] = __floats2half2_rn(e2, e3);
            rsum0 += e0 + e1;
            rsum1 += e2 + e3;
        }
        // reduce across tig lanes (same r0) before touching shared
        rsum0 += __shfl_xor_sync(0xffffffffu, rsum0, 1);
        rsum0 += __shfl_xor_sync(0xffffffffu, rsum0, 2);
        rsum1 += __shfl_xor_sync(0xffffffffu, rsum1, 1);
        rsum1 += __shfl_xor_sync(0xffffffffu, rsum1, 2);
        if (tig == 0) {
            atomicAdd(&rs[r0], rsum0);
            atomicAdd(&rs[r0 + 8], rsum1);
        }
    }
    __syncthreads();
    if (t < 128) atomicAdd(&g_rowsum[bh * Sc + m0 + t], rs[t]);
}

// ---------------------------------------------------------------------------
// Pair-symmetric mix + probs + ctx (TF32 mma). CTA = (b, pair, 64 q rows),
// 32-key chunks (R9 config). E read as fp16 (uint4 = 8 halves per thread).
// grid: (16, 32), 256 threads
// ---------------------------------------------------------------------------
__global__ __launch_bounds__(256) void mixctx_pair_kernel(float* __restrict__ Pout) {
    __shared__ uint32_t Ag[32][68];
    __shared__ uint32_t Ap[32][68];
    __shared__ uint32_t Vg[32][68];
    __shared__ uint32_t Vp[32][68];
    __shared__ float ivg[64], ivp[64], ivgw[64], ivpw[64];

    const int t = threadIdx.x;
    const int lane = t & 31, warp = t >> 5;
    const int gid = lane >> 2, tig = lane & 3;
    const int bp = blockIdx.y;
    const int b = bp >> 3, pr = bp & 7;
    const int g = g_pairA[pr], p = g_pairB[pr];
    const int q0 = blockIdx.x * 64;

    if (t < 64) {
        float rg = g_rowsum[(b * Hc + g) * Sc + q0 + t];
        float rp = g_rowsum[(b * Hc + p) * Sc + q0 + t];
        float w = g_pw[g];
        ivg[t] = 1.f / rg;
        ivp[t] = 1.f / rp;
        ivpw[t] = w / rp;
        ivgw[t] = w / rg;
    }
    __syncthreads();

    const __half* Eg = g_Eh + (size_t)(b * Hc + g) * Sc * Sc;
    const __half* Ep = g_Eh + (size_t)(b * Hc + p) * Sc * Sc;
    const float* VgB = g_V + (size_t)(b * Hc + g) * Sc * HDc;
    const float* VpB = g_V + (size_t)(b * Hc + p) * Sc * HDc;
    float* Pg = Pout + (size_t)(b * Hc + g) * Sc * Sc;
    float* Pp = Pout + (size_t)(b * Hc + p) * Sc * Sc;

    float acc[8][4];
#pragma unroll
    for (int ni = 0; ni < 8; ni++)
#pragma unroll
        for (int j = 0; j < 4; j++) acc[ni][j] = 0.f;

    const int row = t >> 2;                 // 0..63
    const int kbase = (t & 3) * 8;          // 0,8,16,24
    const float vg1 = ivg[row], vpw = ivpw[row];
    const float vp1 = ivp[row], vgw = ivgw[row];
    const int vr = t >> 3, vc0 = (t & 7) * 8;

    for (int kt = 0; kt < Sc; kt += 32) {
        // E chunk (8 halves per head per thread), mix, write probs, stage tf32
        {
            uint4 ug = *(const uint4*)(Eg + (size_t)(q0 + row) * Sc + kt + kbase);
            uint4 up = *(const uint4*)(Ep + (size_t)(q0 + row) * Sc + kt + kbase);
            float2 eg0 = __half22float2(*(__half2*)&ug.x);
            float2 eg1 = __half22float2(*(__half2*)&ug.y);
            float2 eg2 = __half22float2(*(__half2*)&ug.z);
            float2 eg3 = __half22float2(*(__half2*)&ug.w);
            float2 ep0 = __half22float2(*(__half2*)&up.x);
            float2 ep1 = __half22float2(*(__half2*)&up.y);
            float2 ep2 = __half22float2(*(__half2*)&up.z);
            float2 ep3 = __half22float2(*(__half2*)&up.w);
            float egv[8] = {eg0.x, eg0.y, eg1.x, eg1.y, eg2.x, eg2.y, eg3.x, eg3.y};
            float epv[8] = {ep0.x, ep0.y, ep1.x, ep1.y, ep2.x, ep2.y, ep3.x, ep3.y};
            float pgv[8], ppv[8];
#pragma unroll
            for (int i = 0; i < 8; i++) {
                pgv[i] = egv[i] * vg1 + epv[i] * vpw;
                ppv[i] = epv[i] * vp1 + egv[i] * vgw;
            }
            float* PgR = Pg + (size_t)(q0 + row) * Sc + kt + kbase;
            float* PpR = Pp + (size_t)(q0 + row) * Sc + kt + kbase;
            *(float4*)(PgR)     = make_float4(pgv[0], pgv[1], pgv[2], pgv[3]);
            *(float4*)(PgR + 4) = make_float4(pgv[4], pgv[5], pgv[6], pgv[7]);
            *(float4*)(PpR)     = make_float4(ppv[0], ppv[1], ppv[2], ppv[3]);
            *(float4*)(PpR + 4) = make_float4(ppv[4], ppv[5], ppv[6], ppv[7]);
#pragma unroll
            for (int i = 0; i < 8; i++) {
                Ag[kbase + i][row] = f2tf32(pgv[i]);
                Ap[kbase + i][row] = f2tf32(ppv[i]);
            }
        }
        // V chunks [32 k x 64 d] for both heads
#pragma unroll
        for (int i = 0; i < 2; i++) {
            float4 v0 = *(const float4*)&VgB[(size_t)(kt + vr) * HDc + vc0 + 4 * i];
            Vg[vr][vc0 + 4 * i + 0] = f2tf32(v0.x); Vg[vr][vc0 + 4 * i + 1] = f2tf32(v0.y);
            Vg[vr][vc0 + 4 * i + 2] = f2tf32(v0.z); Vg[vr][vc0 + 4 * i + 3] = f2tf32(v0.w);
            float4 v1 = *(const float4*)&VpB[(size_t)(kt + vr) * HDc + vc0 + 4 * i];
            Vp[vr][vc0 + 4 * i + 0] = f2tf32(v1.x); Vp[vr][vc0 + 4 * i + 1] = f2tf32(v1.y);
            Vp[vr][vc0 + 4 * i + 2] = f2tf32(v1.z); Vp[vr][vc0 + 4 * i + 3] = f2tf32(v1.w);
        }
        __syncthreads();

        uint32_t (*Asl)[68] = (warp < 4) ? Ag : Ap;
        uint32_t (*Vsl)[68] = (warp < 4) ? Vg : Vp;
        const int wm = (warp & 3) * 16;
#pragma unroll
        for (int ks = 0; ks < 4; ks++) {
            int kb = ks * 8;
            uint32_t a[4];
            a[0] = Asl[kb + tig][wm + gid];
            a[1] = Asl[kb + tig][wm + gid + 8];
            a[2] = Asl[kb + tig + 4][wm + gid];
            a[3] = Asl[kb + tig + 4][wm + gid + 8];
#pragma unroll
            for (int ni = 0; ni < 8; ni++) {
                uint32_t b0 = Vsl[kb + tig][ni * 8 + gid];
                uint32_t b1 = Vsl[kb + tig + 4][ni * 8 + gid];
                mma_tf32(acc[ni], a, b0, b1);
            }
        }
        __syncthreads();
    }

    const int h = (warp < 4) ? g : p;
    const int wm = (warp & 3) * 16;
    float* Cb = g_ctx + ((size_t)(b * Hc + h) * Sc + q0) * HDc;
#pragma unroll
    for (int ni = 0; ni < 8; ni++) {
        int d = ni * 8 + tig * 2;
        *(float2*)&Cb[(wm + gid) * HDc + d] = make_float2(acc[ni][0], acc[ni][1]);
        *(float2*)&Cb[(wm + gid + 8) * HDc + d] = make_float2(acc[ni][2], acc[ni][3]);
    }
}

// ---------------------------------------------------------------------------
// TF32 output projection: out[4096,1024] = ctx_flat @ Wo^T + bo. grid: (8, 32)
// ---------------------------------------------------------------------------
__global__ __launch_bounds__(256) void gemm_tf32_out(
    const float* __restrict__ W, const float* __restrict__ bias,
    float* __restrict__ Out) {
    __shared__ uint32_t As[128][68];
    __shared__ uint32_t Bs[128][68];
    const int t = threadIdx.x;
    const int lane = t & 31, warp = t >> 5;
    const int gid = lane >> 2, tig = lane & 3;
    const int wm = (warp & 3) * 32, wn = (warp >> 2) * 64;
    const int m0 = blockIdx.y * 128, n0 = blockIdx.x * 128;

    float acc[2][8][4];
#pragma unroll
    for (int mi = 0; mi < 2; mi++)
#pragma unroll
        for (int ni = 0; ni < 8; ni++)
#pragma unroll
            for (int j = 0; j < 4; j++) acc[mi][ni][j] = 0.f;

    for (int k0 = 0; k0 < Ec; k0 += 64) {
#pragma unroll
        for (int i = 0; i < 8; i++) {
            int idx = i * 256 + t;
            int row = idx >> 4, kq = (idx & 15) * 4;
            int k = k0 + kq;
            int m = m0 + row, b = m >> 10, s = m & 1023;
            float4 va = *(const float4*)&g_ctx[((b * Hc + (k >> 6)) * Sc + s) * HDc + (k & 63)];
            GEMM_FILL4(As, row, kq, va);
            float4 vb = *(const float4*)&W[(n0 + row) * Ec + k];
            GEMM_FILL4(Bs, row, kq, vb);
        }
        __syncthreads();
        GEMM_MMA_TILE(As, Bs, acc, wm, wn, gid, tig, 8)
        __syncthreads();
    }

#pragma unroll
    for (int mi = 0; mi < 2; mi++) {
        int r0 = m0 + wm + mi * 16 + gid;
#pragma unroll
        for (int ni = 0; ni < 8; ni++) {
            int col = n0 + wn + ni * 8 + tig * 2;
            float bb0 = bias[col], bb1 = bias[col + 1];
            *(float2*)&Out[r0 * Ec + col] =
                make_float2(acc[mi][ni][0] + bb0, acc[mi][ni][1] + bb1);
            *(float2*)&Out[(r0 + 8) * Ec + col] =
                make_float2(acc[mi][ni][2] + bb0, acc[mi][ni][3] + bb1);
        }
    }
}

// ---------------------------------------------------------------------------
extern "C" void kernel_launch(void* const* d_in, const int* in_sizes, int n_in,
                              void* d_out, int out_size) {
    const float* query    = (const float*)d_in[0];
    const float* key      = (const float*)d_in[1];
    const float* value    = (const float*)d_in[2];
    const float* Wq       = (const float*)d_in[3];
    const float* bq       = (const float*)d_in[4];
    const float* Wk       = (const float*)d_in[5];
    const float* bk       = (const float*)d_in[6];
    const float* Wv       = (const float*)d_in[7];
    const float* bv       = (const float*)d_in[8];
    const float* Wo       = (const float*)d_in[9];
    const float* bo       = (const float*)d_in[10];
    const float* phase    = (const float*)d_in[11];
    const float* hadamard = (const float*)d_in[12];
    const float* ent      = (const float*)d_in[13];

    float* out   = (float*)d_out;
    float* probs = out + OUT_OFF;

    init_misc_kernel<<<1, 256>>>(ent, hadamard, phase, bq, bk);
    zero_rowsum_kernel<<<(Bc * Hc * Sc) / 256, 256>>>();
    wtrans_kernel<<<dim3(Hc, 16, 2), 256>>>(Wq, Wk, hadamard, phase);

    gemm_tf32_proj<<<dim3(Ec / 128, Mc / 128, 3), 256>>>(query, key, value, Wv, bv);

    scores_kernel<<<dim3(Sc / 128, Sc / 128, Bc * Hc), 256>>>();
    mixctx_pair_kernel<<<dim3(Sc / 64, Bc * 8), 256>>>(probs);
    gemm_tf32_out<<<dim3(Ec / 128, Mc / 128), 256>>>(Wo, bo, out);
}

// round 17
// speedup vs baseline: 1.5462x; 1.0197x over previous
#include <cuda_runtime.h>
#include <cuda_fp16.h>
#include <cstdint>

// ---------------------------------------------------------------------------
// QuantumAttention: B=4, S=1024, E=1024, H=16, HD=64
// out  = [B,S,E]           -> d_out[0 .. 4194304)
// probs= [B,H,S,S] (mixed) -> d_out[4194304 .. 71303168)
// Round 16: R15 (best: 664.6us) + mixctx smem staging vectorized:
// A staged [row][key] with STS.128 (conflict-free), V staged via uint4.
// Same values, same mma order -> bit-identical numerics.
// ---------------------------------------------------------------------------

#define Bc 4
#define Sc 1024
#define Ec 1024
#define Hc 16
#define HDc 64
#define Mc (Bc * Sc)           // 4096
#define OUT_OFF (Bc * Sc * Ec) // 4194304

__device__ float g_Wq_eff[Ec * Ec];
__device__ float g_Wk_eff[Ec * Ec];
__device__ float g_bq_eff[Ec];
__device__ float g_bk_eff[Ec];
__device__ float g_Q[Bc * Hc * Sc * HDc];
__device__ float g_K[Bc * Hc * Sc * HDc];
__device__ float g_V[Bc * Hc * Sc * HDc];
__device__ float g_ctx[Bc * Hc * Sc * HDc];
__device__ float g_rowsum[Bc * Hc * Sc];
__device__ __half g_Eh[(size_t)Bc * Hc * Sc * Sc];   // 128 MB scratch (fp16)
__device__ int   g_partner[Hc];
__device__ float g_pw[Hc];
__device__ int   g_pairA[Hc / 2];
__device__ int   g_pairB[Hc / 2];

// ---------------------------------------------------------------------------
__device__ __forceinline__ uint32_t f2tf32(float x) {
    uint32_t r;
    asm("cvt.rna.tf32.f32 %0, %1;" : "=r"(r) : "f"(x));
    return r;
}

__device__ __forceinline__ void mma_tf32(float* c, const uint32_t* a,
                                         uint32_t b0, uint32_t b1) {
    asm volatile(
        "mma.sync.aligned.m16n8k8.row.col.f32.tf32.tf32.f32 "
        "{%0,%1,%2,%3}, {%4,%5,%6,%7}, {%8,%9}, {%0,%1,%2,%3};\n"
        : "+f"(c[0]), "+f"(c[1]), "+f"(c[2]), "+f"(c[3])
        : "r"(a[0]), "r"(a[1]), "r"(a[2]), "r"(a[3]), "r"(b0), "r"(b1));
}

// ---------------------------------------------------------------------------
__global__ void init_misc_kernel(const float* __restrict__ ent,
                                 const float* __restrict__ had,
                                 const float* __restrict__ phase,
                                 const float* __restrict__ bq,
                                 const float* __restrict__ bk) {
    int t = threadIdx.x;
    if (t < Hc) {
        int p = t; float w = 0.f;
        for (int h = 0; h < Hc; h++) {
            if (h != t && ent[h * Hc + t] != 0.f) { p = h; w = ent[h * Hc + t]; }
        }
        g_partner[t] = p;
        g_pw[t] = w;
    }
    __syncthreads();
    if (t == 0) {
        int c = 0;
        for (int g = 0; g < Hc; g++) {
            int p = g_partner[g];
            if (p >= g) { g_pairA[c] = g; g_pairB[c] = p; c++; }
        }
    }
    for (int j = t; j < Ec; j += blockDim.x) {
        int h = j >> 6, e = j & 63;
        float aq = 0.f, ak = 0.f;
        for (int d = 0; d < HDc; d++) {
            float hv = had[d * HDc + e];
            aq += hv * bq[h * HDc + d];
            ak += hv * bk[h * HDc + d];
        }
        float c = cosf(phase[j]);
        g_bq_eff[j] = c * aq;
        g_bk_eff[j] = c * ak;
    }
}

__global__ void zero_rowsum_kernel() {
    int i = blockIdx.x * blockDim.x + threadIdx.x;
    if (i < Bc * Hc * Sc) g_rowsum[i] = 0.f;
}

// ---------------------------------------------------------------------------
// Merged weight transform (z = 0: Wq, z = 1: Wk). grid: (16, 16, 2)
// ---------------------------------------------------------------------------
__global__ __launch_bounds__(256) void wtrans_kernel(const float* __restrict__ Wq,
                                                     const float* __restrict__ Wk,
                                                     const float* __restrict__ had,
                                                     const float* __restrict__ phase) {
    const int which = blockIdx.z;
    const float* W = which ? Wk : Wq;
    float* Weff = which ? g_Wk_eff : g_Wq_eff;
    __shared__ float sH[HDc * 65];
    __shared__ float sW[HDc][68];
    __shared__ float sc[HDc];
    const int h = blockIdx.x;
    const int i0 = blockIdx.y * 64;
    const int t = threadIdx.x;
    for (int j = t; j < HDc * HDc; j += 256) {
        int d = j >> 6, e = j & 63;
        sH[d * 65 + e] = had[j];
    }
    if (t < HDc) sc[t] = cosf(phase[h * HDc + t]);
#pragma unroll
    for (int i = 0; i < 4; i++) {
        int idx = i * 256 + t;
        int d = idx >> 4, q = (idx & 15) * 4;
        *(float4*)&sW[d][q] = *(const float4*)&W[(h * HDc + d) * Ec + i0 + q];
    }
    __syncthreads();

    const int tx = t & 15;
    const int ty = t >> 4;
    float acc[4][4];
#pragma unroll
    for (int a = 0; a < 4; a++)
#pragma unroll
        for (int b = 0; b < 4; b++) acc[a][b] = 0.f;

#pragma unroll 8
    for (int d = 0; d < HDc; d++) {
        float4 w = *(const float4*)&sW[d][tx * 4];
#pragma unroll
        for (int ee = 0; ee < 4; ee++) {
            float hv = sH[d * 65 + ty * 4 + ee];
            acc[ee][0] += hv * w.x;
            acc[ee][1] += hv * w.y;
            acc[ee][2] += hv * w.z;
            acc[ee][3] += hv * w.w;
        }
    }
#pragma unroll
    for (int ee = 0; ee < 4; ee++) {
        int e = ty * 4 + ee;
        float s = sc[e];
        float4 o = make_float4(s * acc[ee][0], s * acc[ee][1],
                               s * acc[ee][2], s * acc[ee][3]);
        *(float4*)&Weff[(h * HDc + e) * Ec + i0 + tx * 4] = o;
    }
}

// ---------------------------------------------------------------------------
// GEMM inner tile: [row][k] layout, stride 68 words (R9, proven).
// ---------------------------------------------------------------------------
#define GEMM_MMA_TILE(As, Bs, acc, wm, wn, gid, tig, NKS)                     \
    _Pragma("unroll")                                                         \
    for (int ks = 0; ks < NKS; ks++) {                                        \
        int kb = ks * 8;                                                      \
        uint32_t a[2][4];                                                     \
        _Pragma("unroll")                                                     \
        for (int mi = 0; mi < 2; mi++) {                                      \
            int r = (wm) + mi * 16 + (gid);                                   \
            a[mi][0] = (As)[r][kb + (tig)];                                   \
            a[mi][1] = (As)[r + 8][kb + (tig)];                               \
            a[mi][2] = (As)[r][kb + (tig) + 4];                               \
            a[mi][3] = (As)[r + 8][kb + (tig) + 4];                           \
        }                                                                     \
        _Pragma("unroll")                                                     \
        for (int ni = 0; ni < 8; ni++) {                                      \
            int c = (wn) + ni * 8 + (gid);                                    \
            uint32_t b0 = (Bs)[c][kb + (tig)];                                \
            uint32_t b1 = (Bs)[c][kb + (tig) + 4];                            \
            mma_tf32(acc[0][ni], a[0], b0, b1);                               \
            mma_tf32(acc[1][ni], a[1], b0, b1);                               \
        }                                                                     \
    }

#define GEMM_FILL4(Sm, row, kq, v)                                            \
    do {                                                                      \
        uint4 _u = make_uint4(f2tf32((v).x), f2tf32((v).y),                   \
                              f2tf32((v).z), f2tf32((v).w));                  \
        *(uint4*)&(Sm)[row][kq] = _u;                                         \
    } while (0)

// ---------------------------------------------------------------------------
// Merged TF32 projection GEMM (z selects q/k/v). grid: (8, 32, 3)
// ---------------------------------------------------------------------------
__global__ __launch_bounds__(256) void gemm_tf32_proj(
    const float* __restrict__ Aq, const float* __restrict__ Ak,
    const float* __restrict__ Av, const float* __restrict__ Wv,
    const float* __restrict__ bv) {
    const int which = blockIdx.z;
    const float* A    = (which == 0) ? Aq : (which == 1) ? Ak : Av;
    const float* W    = (which == 0) ? g_Wq_eff : (which == 1) ? g_Wk_eff : Wv;
    const float* bias = (which == 0) ? g_bq_eff : (which == 1) ? g_bk_eff : bv;
    float* Out        = (which == 0) ? g_Q : (which == 1) ? g_K : g_V;

    __shared__ uint32_t As[128][68];
    __shared__ uint32_t Bs[128][68];
    const int t = threadIdx.x;
    const int lane = t & 31, warp = t >> 5;
    const int gid = lane >> 2, tig = lane & 3;
    const int wm = (warp & 3) * 32, wn = (warp >> 2) * 64;
    const int m0 = blockIdx.y * 128, n0 = blockIdx.x * 128;

    float acc[2][8][4];
#pragma unroll
    for (int mi = 0; mi < 2; mi++)
#pragma unroll
        for (int ni = 0; ni < 8; ni++)
#pragma unroll
            for (int j = 0; j < 4; j++) acc[mi][ni][j] = 0.f;

    for (int k0 = 0; k0 < Ec; k0 += 64) {
#pragma unroll
        for (int i = 0; i < 8; i++) {
            int idx = i * 256 + t;
            int row = idx >> 4, kq = (idx & 15) * 4;
            float4 va = *(const float4*)&A[(m0 + row) * Ec + k0 + kq];
            GEMM_FILL4(As, row, kq, va);
            float4 vb = *(const float4*)&W[(n0 + row) * Ec + k0 + kq];
            GEMM_FILL4(Bs, row, kq, vb);
        }
        __syncthreads();
        GEMM_MMA_TILE(As, Bs, acc, wm, wn, gid, tig, 8)
        __syncthreads();
    }

#pragma unroll
    for (int mi = 0; mi < 2; mi++) {
        int r0 = m0 + wm + mi * 16 + gid;
#pragma unroll
        for (int ni = 0; ni < 8; ni++) {
            int col = n0 + wn + ni * 8 + tig * 2;
            float bb0 = bias[col], bb1 = bias[col + 1];
            int h = col >> 6, d = col & 63;
            {
                int m = r0, b = m >> 10, s = m & 1023;
                *(float2*)&Out[((b * Hc + h) * Sc + s) * HDc + d] =
                    make_float2(acc[mi][ni][0] + bb0, acc[mi][ni][1] + bb1);
            }
            {
                int m = r0 + 8, b = m >> 10, s = m & 1023;
                *(float2*)&Out[((b * Hc + h) * Sc + s) * HDc + d] =
                    make_float2(acc[mi][ni][2] + bb0, acc[mi][ni][3] + bb1);
            }
        }
    }
}

// ---------------------------------------------------------------------------
// TF32 scores: E(fp16) = exp(Q K^T / 8) + fp32 row sums. grid: (8, 8, 64)
// Rowsum partials reduced across the quad (shfl) before shared atomics.
// ---------------------------------------------------------------------------
__global__ __launch_bounds__(256) void scores_kernel() {
    __shared__ uint32_t As[128][68];
    __shared__ uint32_t Bs[128][68];
    __shared__ float rs[128];
    const int t = threadIdx.x;
    const int lane = t & 31, warp = t >> 5;
    const int gid = lane >> 2, tig = lane & 3;
    const int wm = (warp & 3) * 32, wn = (warp >> 2) * 64;
    const int bh = blockIdx.z;
    const int m0 = blockIdx.y * 128, n0 = blockIdx.x * 128;
    const float* Qb = g_Q + (size_t)bh * Sc * HDc;
    const float* Kb = g_K + (size_t)bh * Sc * HDc;

    float acc[2][8][4];
#pragma unroll
    for (int mi = 0; mi < 2; mi++)
#pragma unroll
        for (int ni = 0; ni < 8; ni++)
#pragma unroll
            for (int j = 0; j < 4; j++) acc[mi][ni][j] = 0.f;

#pragma unroll
    for (int i = 0; i < 8; i++) {
        int idx = i * 256 + t;
        int row = idx >> 4, kq = (idx & 15) * 4;
        float4 va = *(const float4*)&Qb[(m0 + row) * HDc + kq];
        GEMM_FILL4(As, row, kq, va);
        float4 vb = *(const float4*)&Kb[(n0 + row) * HDc + kq];
        GEMM_FILL4(Bs, row, kq, vb);
    }
    __syncthreads();
    GEMM_MMA_TILE(As, Bs, acc, wm, wn, gid, tig, 8)

    if (t < 128) rs[t] = 0.f;
    __syncthreads();

    __half* Eb = g_Eh + (size_t)bh * Sc * Sc;
#pragma unroll
    for (int mi = 0; mi < 2; mi++) {
        int r0 = wm + mi * 16 + gid;
        float rsum0 = 0.f, rsum1 = 0.f;
#pragma unroll
        for (int ni = 0; ni < 8; ni++) {
            int col = n0 + wn + ni * 8 + tig * 2;
            float e0 = __expf(acc[mi][ni][0] * 0.125f);
            float e1 = __expf(acc[mi][ni][1] * 0.125f);
            float e2 = __expf(acc[mi][ni][2] * 0.125f);
            float e3 = __expf(acc[mi][ni][3] * 0.125f);
            *(__half2*)&Eb[(size_t)(m0 + r0) * Sc + col]     = __floats2half2_rn(e0, e1);
            *(__half2*)&Eb[(size_t)(m0 + r0 + 8) * Sc + col] = __floats2half2_rn(e2, e3);
            rsum0 += e0 + e1;
            rsum1 += e2 + e3;
        }
        rsum0 += __shfl_xor_sync(0xffffffffu, rsum0, 1);
        rsum0 += __shfl_xor_sync(0xffffffffu, rsum0, 2);
        rsum1 += __shfl_xor_sync(0xffffffffu, rsum1, 1);
        rsum1 += __shfl_xor_sync(0xffffffffu, rsum1, 2);
        if (tig == 0) {
            atomicAdd(&rs[r0], rsum0);
            atomicAdd(&rs[r0 + 8], rsum1);
        }
    }
    __syncthreads();
    if (t < 128) atomicAdd(&g_rowsum[bh * Sc + m0 + t], rs[t]);
}

// ---------------------------------------------------------------------------
// Pair-symmetric mix + probs + ctx (TF32 mma). CTA = (b, pair, 64 q rows),
// 32-key chunks. A staged [row][key] stride 36 (STS.128, conflict-free);
// V staged [key][d] stride 68 via uint4. Values/order identical to R15.
// grid: (16, 32), 256 threads
// ---------------------------------------------------------------------------
__global__ __launch_bounds__(256) void mixctx_pair_kernel(float* __restrict__ Pout) {
    __shared__ uint32_t Ag[64][36];
    __shared__ uint32_t Ap[64][36];
    __shared__ uint32_t Vg[32][68];
    __shared__ uint32_t Vp[32][68];
    __shared__ float ivg[64], ivp[64], ivgw[64], ivpw[64];

    const int t = threadIdx.x;
    const int lane = t & 31, warp = t >> 5;
    const int gid = lane >> 2, tig = lane & 3;
    const int bp = blockIdx.y;
    const int b = bp >> 3, pr = bp & 7;
    const int g = g_pairA[pr], p = g_pairB[pr];
    const int q0 = blockIdx.x * 64;

    if (t < 64) {
        float rg = g_rowsum[(b * Hc + g) * Sc + q0 + t];
        float rp = g_rowsum[(b * Hc + p) * Sc + q0 + t];
        float w = g_pw[g];
        ivg[t] = 1.f / rg;
        ivp[t] = 1.f / rp;
        ivpw[t] = w / rp;
        ivgw[t] = w / rg;
    }
    __syncthreads();

    const __half* Eg = g_Eh + (size_t)(b * Hc + g) * Sc * Sc;
    const __half* Ep = g_Eh + (size_t)(b * Hc + p) * Sc * Sc;
    const float* VgB = g_V + (size_t)(b * Hc + g) * Sc * HDc;
    const float* VpB = g_V + (size_t)(b * Hc + p) * Sc * HDc;
    float* Pg = Pout + (size_t)(b * Hc + g) * Sc * Sc;
    float* Pp = Pout + (size_t)(b * Hc + p) * Sc * Sc;

    float acc[8][4];
#pragma unroll
    for (int ni = 0; ni < 8; ni++)
#pragma unroll
        for (int j = 0; j < 4; j++) acc[ni][j] = 0.f;

    const int row = t >> 2;                 // 0..63
    const int kbase = (t & 3) * 8;          // 0,8,16,24
    const float vg1 = ivg[row], vpw = ivpw[row];
    const float vp1 = ivp[row], vgw = ivgw[row];
    const int vr = t >> 3, vc0 = (t & 7) * 8;

    for (int kt = 0; kt < Sc; kt += 32) {
        // E chunk (8 halves per head per thread), mix, write probs, stage tf32
        {
            uint4 ug = *(const uint4*)(Eg + (size_t)(q0 + row) * Sc + kt + kbase);
            uint4 up = *(const uint4*)(Ep + (size_t)(q0 + row) * Sc + kt + kbase);
            float2 eg0 = __half22float2(*(__half2*)&ug.x);
            float2 eg1 = __half22float2(*(__half2*)&ug.y);
            float2 eg2 = __half22float2(*(__half2*)&ug.z);
            float2 eg3 = __half22float2(*(__half2*)&ug.w);
            float2 ep0 = __half22float2(*(__half2*)&up.x);
            float2 ep1 = __half22float2(*(__half2*)&up.y);
            float2 ep2 = __half22float2(*(__half2*)&up.z);
            float2 ep3 = __half22float2(*(__half2*)&up.w);
            float egv[8] = {eg0.x, eg0.y, eg1.x, eg1.y, eg2.x, eg2.y, eg3.x, eg3.y};
            float epv[8] = {ep0.x, ep0.y, ep1.x, ep1.y, ep2.x, ep2.y, ep3.x, ep3.y};
            float pgv[8], ppv[8];
#pragma unroll
            for (int i = 0; i < 8; i++) {
                pgv[i] = egv[i] * vg1 + epv[i] * vpw;
                ppv[i] = epv[i] * vp1 + egv[i] * vgw;
            }
            float* PgR = Pg + (size_t)(q0 + row) * Sc + kt + kbase;
            float* PpR = Pp + (size_t)(q0 + row) * Sc + kt + kbase;
            *(float4*)(PgR)     = make_float4(pgv[0], pgv[1], pgv[2], pgv[3]);
            *(float4*)(PgR + 4) = make_float4(pgv[4], pgv[5], pgv[6], pgv[7]);
            *(float4*)(PpR)     = make_float4(ppv[0], ppv[1], ppv[2], ppv[3]);
            *(float4*)(PpR + 4) = make_float4(ppv[4], ppv[5], ppv[6], ppv[7]);
            uint4 ag0 = make_uint4(f2tf32(pgv[0]), f2tf32(pgv[1]),
                                   f2tf32(pgv[2]), f2tf32(pgv[3]));
            uint4 ag1 = make_uint4(f2tf32(pgv[4]), f2tf32(pgv[5]),
                                   f2tf32(pgv[6]), f2tf32(pgv[7]));
            uint4 ap0 = make_uint4(f2tf32(ppv[0]), f2tf32(ppv[1]),
                                   f2tf32(ppv[2]), f2tf32(ppv[3]));
            uint4 ap1 = make_uint4(f2tf32(ppv[4]), f2tf32(ppv[5]),
                                   f2tf32(ppv[6]), f2tf32(ppv[7]));
            *(uint4*)&Ag[row][kbase]     = ag0;
            *(uint4*)&Ag[row][kbase + 4] = ag1;
            *(uint4*)&Ap[row][kbase]     = ap0;
            *(uint4*)&Ap[row][kbase + 4] = ap1;
        }
        // V chunks [32 k x 64 d] for both heads (uint4 stores)
#pragma unroll
        for (int i = 0; i < 2; i++) {
            float4 v0 = *(const float4*)&VgB[(size_t)(kt + vr) * HDc + vc0 + 4 * i];
            uint4 u0 = make_uint4(f2tf32(v0.x), f2tf32(v0.y), f2tf32(v0.z), f2tf32(v0.w));
            *(uint4*)&Vg[vr][vc0 + 4 * i] = u0;
            float4 v1 = *(const float4*)&VpB[(size_t)(kt + vr) * HDc + vc0 + 4 * i];
            uint4 u1 = make_uint4(f2tf32(v1.x), f2tf32(v1.y), f2tf32(v1.z), f2tf32(v1.w));
            *(uint4*)&Vp[vr][vc0 + 4 * i] = u1;
        }
        __syncthreads();

        uint32_t (*Asl)[36] = (warp < 4) ? Ag : Ap;
        uint32_t (*Vsl)[68] = (warp < 4) ? Vg : Vp;
        const int wm = (warp & 3) * 16;
#pragma unroll
        for (int ks = 0; ks < 4; ks++) {
            int kb = ks * 8;
            uint32_t a[4];
            a[0] = Asl[wm + gid][kb + tig];
            a[1] = Asl[wm + gid + 8][kb + tig];
            a[2] = Asl[wm + gid][kb + tig + 4];
            a[3] = Asl[wm + gid + 8][kb + tig + 4];
#pragma unroll
            for (int ni = 0; ni < 8; ni++) {
                uint32_t b0 = Vsl[kb + tig][ni * 8 + gid];
                uint32_t b1 = Vsl[kb + tig + 4][ni * 8 + gid];
                mma_tf32(acc[ni], a, b0, b1);
            }
        }
        __syncthreads();
    }

    const int h = (warp < 4) ? g : p;
    const int wm = (warp & 3) * 16;
    float* Cb = g_ctx + ((size_t)(b * Hc + h) * Sc + q0) * HDc;
#pragma unroll
    for (int ni = 0; ni < 8; ni++) {
        int d = ni * 8 + tig * 2;
        *(float2*)&Cb[(wm + gid) * HDc + d] = make_float2(acc[ni][0], acc[ni][1]);
        *(float2*)&Cb[(wm + gid + 8) * HDc + d] = make_float2(acc[ni][2], acc[ni][3]);
    }
}

// ---------------------------------------------------------------------------
// TF32 output projection: out[4096,1024] = ctx_flat @ Wo^T + bo. grid: (8, 32)
// ---------------------------------------------------------------------------
__global__ __launch_bounds__(256) void gemm_tf32_out(
    const float* __restrict__ W, const float* __restrict__ bias,
    float* __restrict__ Out) {
    __shared__ uint32_t As[128][68];
    __shared__ uint32_t Bs[128][68];
    const int t = threadIdx.x;
    const int lane = t & 31, warp = t >> 5;
    const int gid = lane >> 2, tig = lane & 3;
    const int wm = (warp & 3) * 32, wn = (warp >> 2) * 64;
    const int m0 = blockIdx.y * 128, n0 = blockIdx.x * 128;

    float acc[2][8][4];
#pragma unroll
    for (int mi = 0; mi < 2; mi++)
#pragma unroll
        for (int ni = 0; ni < 8; ni++)
#pragma unroll
            for (int j = 0; j < 4; j++) acc[mi][ni][j] = 0.f;

    for (int k0 = 0; k0 < Ec; k0 += 64) {
#pragma unroll
        for (int i = 0; i < 8; i++) {
            int idx = i * 256 + t;
            int row = idx >> 4, kq = (idx & 15) * 4;
            int k = k0 + kq;
            int m = m0 + row, b = m >> 10, s = m & 1023;
            float4 va = *(const float4*)&g_ctx[((b * Hc + (k >> 6)) * Sc + s) * HDc + (k & 63)];
            GEMM_FILL4(As, row, kq, va);
            float4 vb = *(const float4*)&W[(n0 + row) * Ec + k];
            GEMM_FILL4(Bs, row, kq, vb);
        }
        __syncthreads();
        GEMM_MMA_TILE(As, Bs, acc, wm, wn, gid, tig, 8)
        __syncthreads();
    }

#pragma unroll
    for (int mi = 0; mi < 2; mi++) {
        int r0 = m0 + wm + mi * 16 + gid;
#pragma unroll
        for (int ni = 0; ni < 8; ni++) {
            int col = n0 + wn + ni * 8 + tig * 2;
            float bb0 = bias[col], bb1 = bias[col + 1];
            *(float2*)&Out[r0 * Ec + col] =
                make_float2(acc[mi][ni][0] + bb0, acc[mi][ni][1] + bb1);
            *(float2*)&Out[(r0 + 8) * Ec + col] =
                make_float2(acc[mi][ni][2] + bb0, acc[mi][ni][3] + bb1);
        }
    }
}

// ---------------------------------------------------------------------------
extern "C" void kernel_launch(void* const* d_in, const int* in_sizes, int n_in,
                              void* d_out, int out_size) {
    const float* query    = (const float*)d_in[0];
    const float* key      = (const float*)d_in[1];
    const float* value    = (const float*)d_in[2];
    const float* Wq       = (const float*)d_in[3];
    const float* bq       = (const float*)d_in[4];
    const float* Wk       = (const float*)d_in[5];
    const float* bk       = (const float*)d_in[6];
    const float* Wv       = (const float*)d_in[7];
    const float* bv       = (const float*)d_in[8];
    const float* Wo       = (const float*)d_in[9];
    const float* bo       = (const float*)d_in[10];
    const float* phase    = (const float*)d_in[11];
    const float* hadamard = (const float*)d_in[12];
    const float* ent      = (const float*)d_in[13];

    float* out   = (float*)d_out;
    float* probs = out + OUT_OFF;

    init_misc_kernel<<<1, 256>>>(ent, hadamard, phase, bq, bk);
    zero_rowsum_kernel<<<(Bc * Hc * Sc) / 256, 256>>>();
    wtrans_kernel<<<dim3(Hc, 16, 2), 256>>>(Wq, Wk, hadamard, phase);

    gemm_tf32_proj<<<dim3(Ec / 128, Mc / 128, 3), 256>>>(query, key, value, Wv, bv);

    scores_kernel<<<dim3(Sc / 128, Sc / 128, Bc * Hc), 256>>>();
    mixctx_pair_kernel<<<dim3(Sc / 64, Bc * 8), 256>>>(probs);
    gemm_tf32_out<<<dim3(Ec / 128, Mc / 128), 256>>>(Wo, bo, out);
}